// round 4
// baseline (speedup 1.0000x reference)
#include <cuda_runtime.h>

#define K_IN 5
#define OCH 2
#define NN 4096
#define NE 131072
#define TOT (K_IN * NE)       // 655360 edges
#define NQ 4                  // column quarters
#define QC 1024               // columns per quarter
#define PL 25                 // (k,l) planes
#define NB2 (NQ * NN)         // 16384 (quarter,row) bins
#define SMEM_FLOATS (PL * QC + 64)
#define SMEM_BYTES (SMEM_FLOATS * 4)

// ---------------- scratch (device globals; no allocations) ----------------
__device__ float g_ws[2][OCH][K_IN];   // softmax(w1), softmax(w2)
__device__ int   g_cnt1[NN];           // A1 row histogram
__device__ int   g_off1[NN + 1];
__device__ int   g_cur1[NN];
__device__ int   g_cnt2[NB2];          // A2 (quarter,row) histogram
__device__ int   g_off2[NB2 + 1];
__device__ int   g_cur2[NB2];
__device__ int2  g_e1[TOT];            // A1 entry: {col | k<<12, ev bits}
__device__ int2  g_e2[TOT];            // A2 entry: {(col&1023) | k<<10, ev bits}

// ---------------- kernel 1: softmax weights + zero histograms ----------------
__global__ void k_init(const float* __restrict__ w1, const float* __restrict__ w2,
                       float* __restrict__ outw) {
    int t = blockIdx.x * blockDim.x + threadIdx.x;
    for (int i = t; i < NB2; i += gridDim.x * blockDim.x) {
        if (i < NN) g_cnt1[i] = 0;
        g_cnt2[i] = 0;
    }
    if (blockIdx.x == 0 && t < 2 * OCH) {
        int which = t >> 1, o = t & 1;
        const float* w = which ? w2 : w1;
        float v[K_IN];
        float mx = -1e30f;
        #pragma unroll
        for (int k = 0; k < K_IN; k++) { v[k] = w[o * K_IN + k]; mx = fmaxf(mx, v[k]); }
        float s = 0.f;
        #pragma unroll
        for (int k = 0; k < K_IN; k++) { v[k] = expf(v[k] - mx); s += v[k]; }
        float inv = 1.f / s;
        #pragma unroll
        for (int k = 0; k < K_IN; k++) {
            float sv = v[k] * inv;
            g_ws[which][o][k] = sv;
            outw[which * (OCH * K_IN) + o * K_IN + k] = sv;  // W1 then W2
        }
    }
}

// ---------------- kernel 2: histograms ----------------
__global__ void k_hist(const int* __restrict__ ei) {
    int i = blockIdx.x * blockDim.x + threadIdx.x;
    if (i >= TOT) return;
    int k = i / NE, e = i - k * NE;
    int row = ei[(size_t)k * 2 * NE + e];
    int col = ei[(size_t)k * 2 * NE + NE + e];
    atomicAdd(&g_cnt1[row], 1);
    atomicAdd(&g_cnt2[(col >> 10) * NN + row], 1);
}

// ---------------- kernel 3a: scan A1 rows (4096, one block) ----------------
__global__ void k_scan1() {
    __shared__ int s[1024];
    int t = threadIdx.x;
    int c0 = g_cnt1[4 * t + 0], c1 = g_cnt1[4 * t + 1];
    int c2 = g_cnt1[4 * t + 2], c3 = g_cnt1[4 * t + 3];
    int sum = c0 + c1 + c2 + c3;
    s[t] = sum;
    __syncthreads();
    for (int d = 1; d < 1024; d <<= 1) {
        int v = (t >= d) ? s[t - d] : 0;
        __syncthreads();
        s[t] += v;
        __syncthreads();
    }
    int excl = s[t] - sum;
    int o0 = excl, o1 = o0 + c0, o2 = o1 + c1, o3 = o2 + c2;
    g_off1[4 * t + 0] = o0;  g_off1[4 * t + 1] = o1;
    g_off1[4 * t + 2] = o2;  g_off1[4 * t + 3] = o3;
    g_cur1[4 * t + 0] = o0;  g_cur1[4 * t + 1] = o1;
    g_cur1[4 * t + 2] = o2;  g_cur1[4 * t + 3] = o3;
    if (t == 1023) g_off1[NN] = s[1023];
}

// ---------------- kernel 3b: scan A2 (quarter,row) bins (16384, one block) ----------------
__global__ void k_scan2() {
    __shared__ int s[1024];
    int t = threadIdx.x;
    int base = t * 16;
    int v[16];
    int sum = 0;
    #pragma unroll
    for (int i = 0; i < 16; i++) { v[i] = g_cnt2[base + i]; sum += v[i]; }
    s[t] = sum;
    __syncthreads();
    for (int d = 1; d < 1024; d <<= 1) {
        int x = (t >= d) ? s[t - d] : 0;
        __syncthreads();
        s[t] += x;
        __syncthreads();
    }
    int run = s[t] - sum;
    #pragma unroll
    for (int i = 0; i < 16; i++) {
        g_off2[base + i] = run;
        g_cur2[base + i] = run;
        run += v[i];
    }
    if (t == 1023) g_off2[NB2] = s[1023];
}

// ---------------- kernel 4: scatter edges into both CSRs ----------------
__global__ void k_scatter(const int* __restrict__ ei,
                          const float* __restrict__ evals) {
    int i = blockIdx.x * blockDim.x + threadIdx.x;
    if (i >= TOT) return;
    int k = i / NE, e = i - k * NE;
    int row = ei[(size_t)k * 2 * NE + e];
    int col = ei[(size_t)k * 2 * NE + NE + e];
    int evb = __float_as_int(evals[(size_t)k * NE + e]);
    int s1 = atomicAdd(&g_cur1[row], 1);
    g_e1[s1] = make_int2(col | (k << 12), evb);
    int s2 = atomicAdd(&g_cur2[(col >> 10) * NN + row], 1);
    g_e2[s2] = make_int2((col & (QC - 1)) | (k << 10), evb);
}

// ---------------- kernel 5: SpGEMM into 25 (k,l)-planes, 1 atomic per pair ----------
// Block = (output row n, column quarter q). T[p][c] += ev_j * ev_t for every
// pair with type-pair p = k*5+l landing on local column c. Epilogue folds the
// 25 planes into both channels with w1[o,k]*w2[o,l] coefficients.
__global__ void __launch_bounds__(512) k_spgemm(float* __restrict__ H) {
    extern __shared__ float T[];           // PL*QC floats + 64 (coeff table)
    float* co = T + PL * QC;               // co[p] ch0, co[25+p] ch1

    int n = blockIdx.x >> 2;
    int q = blockIdx.x & 3;
    int tid = threadIdx.x;

    // zero planes (float4) + build coefficient table
    float4* T4 = (float4*)T;
    for (int i = tid; i < (PL * QC) / 4; i += 512) T4[i] = make_float4(0.f, 0.f, 0.f, 0.f);
    if (tid < 2 * PL) {
        int o = tid / PL, p = tid - o * PL;
        co[tid] = g_ws[0][o][p / 5] * g_ws[1][o][p % 5];
    }
    __syncthreads();

    int rs = g_off1[n], re = g_off1[n + 1];
    int warp = tid >> 5, lane = tid & 31;
    int grp  = lane >> 3, l8 = lane & 7;
    int gsrc = grp << 3;

    for (int jb = rs + (warp << 2); jb < re; jb += 64) {
        int j = jb + grp;
        int2 e1 = make_int2(0, 0);
        int s2 = 0, e2 = 0;
        if (l8 == 0 && j < re) {
            e1 = g_e1[j];
            int b = (q << 12) + (e1.x & 0xFFF);
            s2 = g_off2[b];
            e2 = g_off2[b + 1];
        }
        e1.x = __shfl_sync(0xFFFFFFFFu, e1.x, gsrc);
        e1.y = __shfl_sync(0xFFFFFFFFu, e1.y, gsrc);
        s2   = __shfl_sync(0xFFFFFFFFu, s2, gsrc);
        e2   = __shfl_sync(0xFFFFFFFFu, e2, gsrc);
        int   k5  = (e1.x >> 12) * 5;
        float evj = __int_as_float(e1.y);
        for (int t = s2 + l8; t < e2; t += 8) {
            int2 p = g_e2[t];
            int idx = ((k5 + (p.x >> 10)) << 10) | (p.x & (QC - 1));
            atomicAdd(&T[idx], evj * __int_as_float(p.y));
        }
    }
    __syncthreads();

    // epilogue: fold 25 planes into 2 channels; thread owns 2 consecutive cols
    float2 h0 = make_float2(0.f, 0.f), h1 = make_float2(0.f, 0.f);
    int c2 = tid << 1;
    #pragma unroll
    for (int p = 0; p < PL; p++) {
        float2 tv = *(const float2*)&T[(p << 10) + c2];
        float a = co[p], b = co[PL + p];
        h0.x += a * tv.x;  h0.y += a * tv.y;
        h1.x += b * tv.x;  h1.y += b * tv.y;
    }
    size_t base = (size_t)n * NN + (q << 10) + c2;
    *(float2*)&H[base] = h0;
    *(float2*)&H[(size_t)NN * NN + base] = h1;
}

// ---------------- launch ----------------
extern "C" void kernel_launch(void* const* d_in, const int* in_sizes, int n_in,
                              void* d_out, int out_size) {
    const int*   ei = (const int*)d_in[0];     // edge_index [5,2,E] int32
    const float* ev = (const float*)d_in[1];   // edge_value [5,E]
    const float* w1 = (const float*)d_in[2];   // [2,5]
    const float* w2 = (const float*)d_in[3];   // [2,5]
    float* out = (float*)d_out;
    const size_t H_ELEMS = (size_t)OCH * NN * NN;

    cudaFuncSetAttribute(k_spgemm, cudaFuncAttributeMaxDynamicSharedMemorySize,
                         SMEM_BYTES);

    k_init<<<32, 256>>>(w1, w2, out + H_ELEMS);
    k_hist<<<(TOT + 255) / 256, 256>>>(ei);
    k_scan1<<<1, 1024>>>();
    k_scan2<<<1, 1024>>>();
    k_scatter<<<(TOT + 255) / 256, 256>>>(ei, ev);
    k_spgemm<<<NN * NQ, 512, SMEM_BYTES>>>(out);
}